// round 2
// baseline (speedup 1.0000x reference)
#include <cuda_runtime.h>
#include <cstdint>
#include <math.h>

#define DEV_INLINE __device__ __forceinline__

static constexpr int B_ = 16, C_ = 256, H_ = 128, W_ = 128;
static constexpr int CS = 512;
static constexpr int TOK_HF = 1024;              // 32x32 tokens per (band,b)
static constexpr int M_HF = 3 * B_ * TOK_HF;     // 49152
static constexpr int M_LF = B_ * 256;            // 4096

// ---------------- scratch (no allocations allowed) ----------------
__device__ float g_z[3ULL * B_ * C_ * TOK_HF];       // [band][b][c][tok]
__device__ float g_ps[(size_t)B_ * CS * 256];        // [b][s][tok]
__device__ float g_H[(size_t)M_HF * 512];            // LN-ed hidden (hf)
__device__ float g_Hlf[(size_t)M_LF * 512];
__device__ float g_ktok[(size_t)M_LF * C_];
__device__ float g_gate[(size_t)M_LF * C_];          // [b][tok][c]
__device__ float g_alpha[3 * B_ * TOK_HF];

// ---------------- K1: Haar bands -> abs-pooled z tokens ----------------
__global__ void haar_z_kernel(const float* __restrict__ xb)
{
    __shared__ float4 xs[4][32];
    int ti = blockIdx.x, c = blockIdx.y, b = blockIdx.z;
    const float4* src = (const float4*)(xb + (((size_t)(b * C_ + c)) * H_ + 4 * ti) * W_);
    int t = threadIdx.x;
    xs[t >> 5][t & 31] = src[t];
    __syncthreads();
    if (t < 32) {
        float4 x0 = xs[0][t], x1 = xs[1][t], x2 = xs[2][t], x3 = xs[3][t];
        float zh = 0.f, zv = 0.f, zd = 0.f;
        {   float p00 = x0.x, p01 = x0.y, p10 = x1.x, p11 = x1.y;
            zh += fabsf(p00 - p01 + p10 - p11);
            zv += fabsf(p00 + p01 - p10 - p11);
            zd += fabsf(p00 - p01 - p10 + p11); }
        {   float p00 = x0.z, p01 = x0.w, p10 = x1.z, p11 = x1.w;
            zh += fabsf(p00 - p01 + p10 - p11);
            zv += fabsf(p00 + p01 - p10 - p11);
            zd += fabsf(p00 - p01 - p10 + p11); }
        {   float p00 = x2.x, p01 = x2.y, p10 = x3.x, p11 = x3.y;
            zh += fabsf(p00 - p01 + p10 - p11);
            zv += fabsf(p00 + p01 - p10 - p11);
            zd += fabsf(p00 - p01 - p10 + p11); }
        {   float p00 = x2.z, p01 = x2.w, p10 = x3.z, p11 = x3.w;
            zh += fabsf(p00 - p01 + p10 - p11);
            zv += fabsf(p00 + p01 - p10 - p11);
            zd += fabsf(p00 - p01 - p10 + p11); }
        const float s = 0.0625f;  // 0.25 (haar) * 0.25 (mean of 4)
        size_t base = (((size_t)b) * C_ + c) * TOK_HF + ti * 32 + t;
        const size_t BS = (size_t)B_ * C_ * TOK_HF;
        g_z[base]          = zh * s;
        g_z[BS + base]     = zv * s;
        g_z[2 * BS + base] = zd * s;
    }
}

// ---------------- K2: 4x4 mean-pool of x_small ----------------
__global__ void pool_small_kernel(const float* __restrict__ xsm)
{
    int s = blockIdx.x, b = blockIdx.y;
    const float* src = xsm + ((size_t)(b * CS + s)) * 64 * 64;
    int t = threadIdx.x;
    int tj = t & 15, ti = t >> 4;
    float sum = 0.f;
#pragma unroll
    for (int r = 0; r < 4; r++) {
        float4 v = *(const float4*)(src + (4 * ti + r) * 64 + 4 * tj);
        sum += v.x + v.y + v.z + v.w;
    }
    g_ps[((size_t)(b * CS + s)) * 256 + t] = sum * (1.f / 16.f);
}

// ---------------- tf32 mma helpers ----------------
DEV_INLINE unsigned f2tf(float f) {
    unsigned u; asm("cvt.rna.tf32.f32 %0, %1;" : "=r"(u) : "f"(f)); return u;
}
DEV_INLINE void mma8(float* c, const unsigned* a, const unsigned* b) {
    asm volatile("mma.sync.aligned.m16n8k8.row.col.f32.tf32.tf32.f32 "
                 "{%0,%1,%2,%3}, {%4,%5,%6,%7}, {%8,%9}, {%0,%1,%2,%3};"
                 : "+f"(c[0]), "+f"(c[1]), "+f"(c[2]), "+f"(c[3])
                 : "r"(a[0]), "r"(a[1]), "r"(a[2]), "r"(a[3]),
                   "r"(b[0]), "r"(b[1]));
}

// ---------------- fused GEMM: C = A(64xK tile) @ B(KxN) ----------------
// AMODE: 0 = z layout ([blk][k][1024]), 1 = ps layout ([b][k][256]), 2 = row-major.
// EPI: 0 = +bias store, 1 = +bias LN store, 2 = +bias cos-sim->relu, 3 = +bias sigmoid.
template<int K, int N, int AMODE, int EPI>
__global__ void __launch_bounds__(512)
gemm_kernel(const float* __restrict__ A, const float* __restrict__ Bw,
            const float* __restrict__ bias, const float* __restrict__ p0,
            const float* __restrict__ p1, float* __restrict__ out)
{
    constexpr int WARPS_N = N / 64;
    constexpr int WARPS_M = 16 / WARPS_N;
    constexpr int WM = 64 / WARPS_M;
    constexpr int MT = WM / 16;
    constexpr int KC = 16;
    constexpr int AP = 72;       // %32==8 -> conflict-free frag loads
    constexpr int BP = N + 8;

    __shared__ unsigned As[KC][AP];
    __shared__ unsigned Bs[KC][BP];
    __shared__ float sred[64][WARPS_N];
    __shared__ float ssred[64][WARPS_N];
    __shared__ float spn;

    int tid = threadIdx.x;
    int lane = tid & 31, warp = tid >> 5;
    int wn = warp % WARPS_N, wm = warp / WARPS_N;
    int gid = lane >> 2, q4 = lane & 3;
    int m0 = blockIdx.x * 64;

    const float* Ab; int astride;
    if (AMODE == 0) { Ab = A + (size_t)(m0 >> 10) * (C_ * TOK_HF) + (m0 & 1023); astride = TOK_HF; }
    else if (AMODE == 1) { Ab = A + (size_t)(m0 >> 8) * (CS * 256) + (m0 & 255); astride = 256; }
    else { Ab = A + (size_t)m0 * K; astride = K; }

    if (EPI == 2 && warp == 0) {
        float s = 0.f;
        for (int i = lane; i < N; i += 32) { float v = p0[i]; s += v * v; }
#pragma unroll
        for (int o = 16; o; o >>= 1) s += __shfl_xor_sync(0xffffffffu, s, o);
        if (lane == 0) spn = sqrtf(s);
    }

    float acc[MT][8][4];
#pragma unroll
    for (int mi = 0; mi < MT; mi++)
#pragma unroll
        for (int ni = 0; ni < 8; ni++)
#pragma unroll
            for (int e = 0; e < 4; e++) acc[mi][ni][e] = 0.f;

    for (int k0 = 0; k0 < K; k0 += KC) {
        if (AMODE <= 1) {
            if (tid < 256) {
                int kr = tid >> 4, mf = (tid & 15) << 2;
                float4 v = *(const float4*)(Ab + (size_t)(k0 + kr) * astride + mf);
                As[kr][mf]     = f2tf(v.x); As[kr][mf + 1] = f2tf(v.y);
                As[kr][mf + 2] = f2tf(v.z); As[kr][mf + 3] = f2tf(v.w);
            }
        } else {
            if (tid < 256) {
                int kg = (tid & 3) << 2, m = tid >> 2;
                float4 v = *(const float4*)(Ab + (size_t)m * K + k0 + kg);
                As[kg][m]     = f2tf(v.x); As[kg + 1][m] = f2tf(v.y);
                As[kg + 2][m] = f2tf(v.z); As[kg + 3][m] = f2tf(v.w);
            }
        }
        {
            constexpr int ITEMS = (KC * N / 4) / 512;
#pragma unroll
            for (int it = 0; it < ITEMS; it++) {
                int idx = tid + it * 512;
                int kr = idx / (N / 4), nf = (idx % (N / 4)) << 2;
                float4 v = *(const float4*)(Bw + (size_t)(k0 + kr) * N + nf);
                Bs[kr][nf]     = f2tf(v.x); Bs[kr][nf + 1] = f2tf(v.y);
                Bs[kr][nf + 2] = f2tf(v.z); Bs[kr][nf + 3] = f2tf(v.w);
            }
        }
        __syncthreads();
#pragma unroll
        for (int kk = 0; kk < KC; kk += 8) {
            unsigned afr[MT][4];
#pragma unroll
            for (int mi = 0; mi < MT; mi++) {
                int mr = wm * WM + mi * 16 + gid;
                afr[mi][0] = As[kk + q4][mr];
                afr[mi][1] = As[kk + q4][mr + 8];
                afr[mi][2] = As[kk + q4 + 4][mr];
                afr[mi][3] = As[kk + q4 + 4][mr + 8];
            }
            unsigned bfr[8][2];
#pragma unroll
            for (int ni = 0; ni < 8; ni++) {
                int nc = wn * 64 + ni * 8 + gid;
                bfr[ni][0] = Bs[kk + q4][nc];
                bfr[ni][1] = Bs[kk + q4 + 4][nc];
            }
#pragma unroll
            for (int mi = 0; mi < MT; mi++)
#pragma unroll
                for (int ni = 0; ni < 8; ni++)
                    mma8(acc[mi][ni], afr[mi], bfr[ni]);
        }
        __syncthreads();
    }

    // ---- epilogue ----
    float rs[MT][2], rss[MT][2];
#pragma unroll
    for (int mi = 0; mi < MT; mi++) { rs[mi][0] = rs[mi][1] = 0.f; rss[mi][0] = rss[mi][1] = 0.f; }

#pragma unroll
    for (int mi = 0; mi < MT; mi++)
#pragma unroll
        for (int ni = 0; ni < 8; ni++)
#pragma unroll
            for (int e4 = 0; e4 < 4; e4++) {
                int h = e4 >> 1, e = e4 & 1;
                int col = wn * 64 + ni * 8 + q4 * 2 + e;
                float v = acc[mi][ni][e4] + __ldg(bias + col);
                acc[mi][ni][e4] = v;
                if (EPI == 1) { rs[mi][h] += v; rss[mi][h] += v * v; }
                if (EPI == 2) { rs[mi][h] += v * __ldg(p0 + col); rss[mi][h] += v * v; }
            }

    if (EPI == 1 || EPI == 2) {
#pragma unroll
        for (int mi = 0; mi < MT; mi++)
#pragma unroll
            for (int h = 0; h < 2; h++) {
                float s = rs[mi][h], ss = rss[mi][h];
                s  += __shfl_xor_sync(0xffffffffu, s, 1);
                s  += __shfl_xor_sync(0xffffffffu, s, 2);
                ss += __shfl_xor_sync(0xffffffffu, ss, 1);
                ss += __shfl_xor_sync(0xffffffffu, ss, 2);
                if (q4 == 0) {
                    int lr = wm * WM + mi * 16 + gid + h * 8;
                    sred[lr][wn] = s; ssred[lr][wn] = ss;
                }
            }
        __syncthreads();
    }

    if (EPI == 1) {
        float mu[MT][2], rstd[MT][2];
#pragma unroll
        for (int mi = 0; mi < MT; mi++)
#pragma unroll
            for (int h = 0; h < 2; h++) {
                int lr = wm * WM + mi * 16 + gid + h * 8;
                float s = 0.f, ss = 0.f;
#pragma unroll
                for (int j = 0; j < WARPS_N; j++) { s += sred[lr][j]; ss += ssred[lr][j]; }
                float m = s * (1.f / N);
                float var = ss * (1.f / N) - m * m;
                mu[mi][h] = m; rstd[mi][h] = rsqrtf(var + 1e-5f);
            }
#pragma unroll
        for (int mi = 0; mi < MT; mi++)
#pragma unroll
            for (int ni = 0; ni < 8; ni++) {
                int col = wn * 64 + ni * 8 + q4 * 2;
                float w0 = __ldg(p0 + col), w1 = __ldg(p0 + col + 1);
                float c0 = __ldg(p1 + col), c1 = __ldg(p1 + col + 1);
#pragma unroll
                for (int h = 0; h < 2; h++) {
                    int lr = wm * WM + mi * 16 + gid + h * 8;
                    float2 o;
                    o.x = (acc[mi][ni][h * 2 + 0] - mu[mi][h]) * rstd[mi][h] * w0 + c0;
                    o.y = (acc[mi][ni][h * 2 + 1] - mu[mi][h]) * rstd[mi][h] * w1 + c1;
                    *(float2*)(out + (size_t)(m0 + lr) * N + col) = o;
                }
            }
    }
    if (EPI == 2) {
        if (tid < 64) {
            float dot = 0.f, nsq = 0.f;
#pragma unroll
            for (int j = 0; j < WARPS_N; j++) { dot += sred[tid][j]; nsq += ssred[tid][j]; }
            float nq = sqrtf(nsq);
            float sim = dot / (fmaxf(nq, 1e-8f) * fmaxf(spn, 1e-8f));
            out[m0 + tid] = fmaxf(sim, 0.f);
        }
    }
    if (EPI == 0 || EPI == 3) {
#pragma unroll
        for (int mi = 0; mi < MT; mi++)
#pragma unroll
            for (int ni = 0; ni < 8; ni++) {
                int col = wn * 64 + ni * 8 + q4 * 2;
#pragma unroll
                for (int h = 0; h < 2; h++) {
                    int lr = wm * WM + mi * 16 + gid + h * 8;
                    float vx = acc[mi][ni][h * 2 + 0], vy = acc[mi][ni][h * 2 + 1];
                    if (EPI == 3) { vx = 1.f / (1.f + expf(-vx)); vy = 1.f / (1.f + expf(-vy)); }
                    *(float2*)(out + (size_t)(m0 + lr) * N + col) = make_float2(vx, vy);
                }
            }
    }
}

// ---------------- K5: apply alpha/gate, inverse Haar, write output ----------------
__global__ void final_kernel(const float* __restrict__ xb, float* __restrict__ out)
{
    __shared__ __align__(16) float xs[4][128];
    int ti = blockIdx.x, c = blockIdx.y, b = blockIdx.z;
    size_t img = ((size_t)(b * C_ + c)) * H_;
    const float4* src = (const float4*)(xb + (img + 4 * ti) * W_);
    int t = threadIdx.x;
    ((float4*)xs)[t] = src[t];
    __syncthreads();
    int r = t >> 6, j = t & 63;
    float2 top = ((float2*)xs[2 * r])[j];
    float2 bot = ((float2*)xs[2 * r + 1])[j];
    float p00 = top.x, p01 = top.y, p10 = bot.x, p11 = bot.y;
    float a  = 0.25f * (p00 + p01 + p10 + p11);
    float hb = 0.25f * (p00 - p01 + p10 - p11);
    float vb = 0.25f * (p00 + p01 - p10 - p11);
    float db = 0.25f * (p00 - p01 - p10 + p11);
    int tok = ti * 32 + (j >> 1);
    float ah = __ldg(&g_alpha[(0 * B_ + b) * TOK_HF + tok]);
    float av = __ldg(&g_alpha[(1 * B_ + b) * TOK_HF + tok]);
    float ad = __ldg(&g_alpha[(2 * B_ + b) * TOK_HF + tok]);
    int tg = (ti >> 1) * 16 + (j >> 2);
    float gt = __ldg(&g_gate[((size_t)(b * 256 + tg)) * C_ + c]);
    float ae = a * gt, he = hb * ah, ve = vb * av, de = db * ad;
    float2 o0 = make_float2(ae + he + ve + de, ae - he + ve - de);
    float2 o1 = make_float2(ae + he - ve - de, ae - he - ve + de);
    int row0 = 4 * ti + 2 * r;
    ((float2*)(out + (img + row0) * W_))[j] = o0;
    ((float2*)(out + (img + row0 + 1) * W_))[j] = o1;
}

extern "C" void kernel_launch(void* const* d_in, const int* in_sizes, int n_in,
                              void* d_out, int out_size)
{
    const float* xb      = (const float*)d_in[0];
    const float* xsm     = (const float*)d_in[1];
    const float* hf_w1   = (const float*)d_in[2];
    const float* hf_b1   = (const float*)d_in[3];
    const float* hf_ln_w = (const float*)d_in[4];
    const float* hf_ln_b = (const float*)d_in[5];
    const float* hf_w2   = (const float*)d_in[6];
    const float* hf_b2   = (const float*)d_in[7];
    const float* hf_pr   = (const float*)d_in[8];
    const float* low_w   = (const float*)d_in[9];
    const float* low_b   = (const float*)d_in[10];
    const float* lf_w1   = (const float*)d_in[11];
    const float* lf_b1   = (const float*)d_in[12];
    const float* lf_ln_w = (const float*)d_in[13];
    const float* lf_ln_b = (const float*)d_in[14];
    const float* lf_w2   = (const float*)d_in[15];
    const float* lf_b2   = (const float*)d_in[16];

    void *pz, *pps, *pH, *pHlf, *pktok, *pgate, *palpha;
    cudaGetSymbolAddress(&pz, g_z);
    cudaGetSymbolAddress(&pps, g_ps);
    cudaGetSymbolAddress(&pH, g_H);
    cudaGetSymbolAddress(&pHlf, g_Hlf);
    cudaGetSymbolAddress(&pktok, g_ktok);
    cudaGetSymbolAddress(&pgate, g_gate);
    cudaGetSymbolAddress(&palpha, g_alpha);

    haar_z_kernel<<<dim3(32, 256, 16), 128>>>(xb);
    pool_small_kernel<<<dim3(512, 16), 256>>>(xsm);

    // hf chain
    gemm_kernel<256, 512, 0, 1><<<M_HF / 64, 512>>>(
        (const float*)pz, hf_w1, hf_b1, hf_ln_w, hf_ln_b, (float*)pH);
    gemm_kernel<512, 256, 2, 2><<<M_HF / 64, 512>>>(
        (const float*)pH, hf_w2, hf_b2, hf_pr, nullptr, (float*)palpha);

    // lf chain
    gemm_kernel<512, 256, 1, 0><<<M_LF / 64, 512>>>(
        (const float*)pps, low_w, low_b, nullptr, nullptr, (float*)pktok);
    gemm_kernel<256, 512, 2, 1><<<M_LF / 64, 512>>>(
        (const float*)pktok, lf_w1, lf_b1, lf_ln_w, lf_ln_b, (float*)pHlf);
    gemm_kernel<512, 256, 2, 3><<<M_LF / 64, 512>>>(
        (const float*)pHlf, lf_w2, lf_b2, nullptr, nullptr, (float*)pgate);

    final_kernel<<<dim3(32, 256, 16), 128>>>(xb, (float*)d_out);
}

// round 3
// speedup vs baseline: 1.5609x; 1.5609x over previous
#include <cuda_runtime.h>
#include <cstdint>
#include <math.h>

#define DEV_INLINE __device__ __forceinline__

static constexpr int B_ = 16, C_ = 256, H_ = 128, W_ = 128;
static constexpr int CS = 512;
static constexpr int TOK_HF = 1024;
static constexpr int M_HF = 3 * B_ * TOK_HF;     // 49152
static constexpr int M_LF = B_ * 256;            // 4096

// ---------------- scratch ----------------
__device__ float g_z[3ULL * B_ * C_ * TOK_HF];       // [band][b][c][tok]
__device__ float g_ps[(size_t)B_ * CS * 256];        // [b][s][tok]
__device__ float g_H[(size_t)M_HF * 512];
__device__ float g_Hlf[(size_t)M_LF * 512];
__device__ float g_ktok[(size_t)M_LF * C_];
__device__ float g_gate[(size_t)M_LF * C_];
__device__ float g_alpha[3 * B_ * TOK_HF];
__device__ float g_wt[5ULL * 512 * 256];             // transposed weights [n][k]

// ---------------- weight transpose (5 matrices -> [n][k]) ----------------
__global__ void transpose5_kernel(const float* __restrict__ w0, const float* __restrict__ w1,
                                  const float* __restrict__ w2, const float* __restrict__ w3,
                                  const float* __restrict__ w4)
{
    __shared__ float tile[32][33];
    int mi = blockIdx.z;
    const float* in; int R, Cc;
    switch (mi) {
        case 0: in = w0; R = 256; Cc = 512; break;   // hf_w1
        case 1: in = w1; R = 512; Cc = 256; break;   // hf_w2
        case 2: in = w2; R = 512; Cc = 256; break;   // low_w
        case 3: in = w3; R = 256; Cc = 512; break;   // lf_w1
        default: in = w4; R = 512; Cc = 256; break;  // lf_w2
    }
    float* out = g_wt + (size_t)mi * 512 * 256;
    int bx = blockIdx.x * 32, by = blockIdx.y * 32;
    if (bx >= Cc || by >= R) return;
    int tx = threadIdx.x, ty = threadIdx.y;
#pragma unroll
    for (int j = 0; j < 32; j += 8)
        tile[ty + j][tx] = in[(size_t)(by + ty + j) * Cc + bx + tx];
    __syncthreads();
#pragma unroll
    for (int j = 0; j < 32; j += 8)
        out[(size_t)(bx + ty + j) * R + by + tx] = tile[tx][ty + j];
}

// ---------------- K1: Haar bands -> abs-pooled z tokens ----------------
__global__ void haar_z_kernel(const float* __restrict__ xb)
{
    int tid = threadIdx.x;
    int tk = blockIdx.x * 256 + tid;          // token 0..1023
    int c = blockIdx.y, b = blockIdx.z;
    int ti = tk >> 5, tj = tk & 31;
    const float* base = xb + ((size_t)(b * C_ + c) * H_ + 4 * ti) * W_ + 4 * tj;
    float4 r0 = *(const float4*)(base);
    float4 r1 = *(const float4*)(base + W_);
    float4 r2 = *(const float4*)(base + 2 * W_);
    float4 r3 = *(const float4*)(base + 3 * W_);
    float zh = 0.f, zv = 0.f, zd = 0.f;
#define HBLK(p00, p01, p10, p11) \
    zh += fabsf((p00) - (p01) + (p10) - (p11)); \
    zv += fabsf((p00) + (p01) - (p10) - (p11)); \
    zd += fabsf((p00) - (p01) - (p10) + (p11));
    HBLK(r0.x, r0.y, r1.x, r1.y)
    HBLK(r0.z, r0.w, r1.z, r1.w)
    HBLK(r2.x, r2.y, r3.x, r3.y)
    HBLK(r2.z, r2.w, r3.z, r3.w)
#undef HBLK
    const float s = 0.0625f;
    size_t base_o = ((size_t)(b) * C_ + c) * TOK_HF + tk;
    const size_t BS = (size_t)B_ * C_ * TOK_HF;
    g_z[base_o]          = zh * s;
    g_z[BS + base_o]     = zv * s;
    g_z[2 * BS + base_o] = zd * s;
}

// ---------------- K2: 4x4 mean-pool of x_small ----------------
__global__ void pool_small_kernel(const float* __restrict__ xsm)
{
    int s = blockIdx.x, b = blockIdx.y;
    const float* src = xsm + ((size_t)(b * CS + s)) * 64 * 64;
    int t = threadIdx.x;
    int tj = t & 15, ti = t >> 4;
    float sum = 0.f;
#pragma unroll
    for (int r = 0; r < 4; r++) {
        float4 v = *(const float4*)(src + (4 * ti + r) * 64 + 4 * tj);
        sum += v.x + v.y + v.z + v.w;
    }
    g_ps[((size_t)(b * CS + s)) * 256 + t] = sum * (1.f / 16.f);
}

// ---------------- asm helpers ----------------
DEV_INLINE void mma8(float* c, const unsigned* a, const unsigned* b) {
    asm volatile("mma.sync.aligned.m16n8k8.row.col.f32.tf32.tf32.f32 "
                 "{%0,%1,%2,%3}, {%4,%5,%6,%7}, {%8,%9}, {%0,%1,%2,%3};"
                 : "+f"(c[0]), "+f"(c[1]), "+f"(c[2]), "+f"(c[3])
                 : "r"(a[0]), "r"(a[1]), "r"(a[2]), "r"(a[3]),
                   "r"(b[0]), "r"(b[1]));
}
DEV_INLINE void ldsm4(unsigned& r0, unsigned& r1, unsigned& r2, unsigned& r3, uint32_t addr) {
    asm volatile("ldmatrix.sync.aligned.m8n8.x4.shared.b16 {%0,%1,%2,%3}, [%4];"
                 : "=r"(r0), "=r"(r1), "=r"(r2), "=r"(r3) : "r"(addr));
}
DEV_INLINE void cp16(uint32_t s, const void* g) {
    asm volatile("cp.async.cg.shared.global [%0], [%1], 16;" :: "r"(s), "l"(g));
}
DEV_INLINE void cp_commit() { asm volatile("cp.async.commit_group;"); }
template<int NN> DEV_INLINE void cp_wait() { asm volatile("cp.async.wait_group %0;" :: "n"(NN)); }

// ---------------- fused GEMM (ldmatrix + cp.async double buffer) ----------------
// C = A(64xK) @ Bt^T, Bt stored [n][k].  AMODE: 0 z-layout, 1 ps-layout, 2 row-major.
// EPI: 0 bias, 1 bias+LN, 2 bias+cos-sim->relu, 3 bias+sigmoid.
template<int K, int N, int AMODE, int EPI>
__global__ void __launch_bounds__(512, 1)
gemm_kernel(const float* __restrict__ A, const float* __restrict__ Bt,
            const float* __restrict__ bias, const float* __restrict__ p0,
            const float* __restrict__ p1, float* __restrict__ out)
{
    constexpr int WARPS_N = N / 64;
    constexpr int WARPS_M = 16 / WARPS_N;
    constexpr int WM = 64 / WARPS_M;
    constexpr int MT = WM / 16;
    constexpr int KC = 16;
    constexpr int SW = KC + 4;     // 20 words = 80B row stride
    constexpr int SWB = SW * 4;
    constexpr int NIT = K / KC;

    extern __shared__ __align__(16) char dsm[];
    float* As   = (float*)dsm;                     // 2 * 64 * SW
    float* Bs   = As + 2 * 64 * SW;                // 2 * N * SW
    float* sred = Bs + 2 * N * SW;
    float* ssred = sred + 64 * WARPS_N;
    float* spn  = ssred + 64 * WARPS_N;

    int tid = threadIdx.x;
    int lane = tid & 31, warp = tid >> 5;
    int wn = warp % WARPS_N, wm = warp / WARPS_N;
    int gid = lane >> 2, q4 = lane & 3;
    int m0 = blockIdx.x * 64;

    const float* Ab; int astride = 0;
    if (AMODE == 0) { Ab = A + (size_t)(m0 >> 10) * (C_ * TOK_HF) + (m0 & 1023); astride = TOK_HF; }
    else if (AMODE == 1) { Ab = A + (size_t)(m0 >> 8) * (CS * 256) + (m0 & 255); astride = 256; }
    else { Ab = A + (size_t)m0 * K; }

    if (EPI == 2 && warp == 0) {
        float s = 0.f;
        for (int i = lane; i < N; i += 32) { float v = p0[i]; s += v * v; }
#pragma unroll
        for (int o = 16; o; o >>= 1) s += __shfl_xor_sync(0xffffffffu, s, o);
        if (lane == 0) *spn = sqrtf(s);
    }

    uint32_t smem_a = (uint32_t)__cvta_generic_to_shared(As);
    uint32_t smem_b = (uint32_t)__cvta_generic_to_shared(Bs);

    // A-load thread mapping
    int la_m, la_kg;
    if (AMODE <= 1) { la_m = tid & 63; la_kg = tid >> 6; }      // tid<256
    else            { la_m = tid >> 2; la_kg = tid & 3; }

    float areg[4];
    auto load_A = [&](int k0) {
        if (tid < 256) {
            if (AMODE <= 1) {
#pragma unroll
                for (int i = 0; i < 4; i++)
                    areg[i] = __ldg(Ab + (size_t)(k0 + la_kg * 4 + i) * astride + la_m);
            } else {
                float4 v = *(const float4*)(Ab + (size_t)la_m * K + k0 + la_kg * 4);
                areg[0] = v.x; areg[1] = v.y; areg[2] = v.z; areg[3] = v.w;
            }
        }
    };
    auto sts_A = [&](int st) {
        if (tid < 256)
            *(float4*)(As + st * 64 * SW + la_m * SW + la_kg * 4) =
                make_float4(areg[0], areg[1], areg[2], areg[3]);
    };
    auto cp_B = [&](int st, int k0) {
        constexpr int CHUNKS = N * 4;                 // 16B chunks per stage
#pragma unroll
        for (int j = 0; j < CHUNKS / 512; j++) {
            int idx = tid + j * 512;
            int n = idx >> 2, kc = idx & 3;
            cp16(smem_b + (uint32_t)((st * N + n) * SW + kc * 4) * 4,
                 Bt + (size_t)n * K + k0 + kc * 4);
        }
        cp_commit();
    };

    // fragment address lanes
    int ra = lane & 15;
    int ca = (lane & 16) ? 16 : 0;
    int rb = (lane & 7) + ((lane >> 4) << 3);
    int cb = (lane & 8) ? 16 : 0;

    float acc[MT][8][4];
#pragma unroll
    for (int mi = 0; mi < MT; mi++)
#pragma unroll
        for (int ni = 0; ni < 8; ni++)
#pragma unroll
            for (int e = 0; e < 4; e++) acc[mi][ni][e] = 0.f;

    // prologue: stage 0
    load_A(0); cp_B(0, 0); sts_A(0);

    for (int it = 0; it < NIT; it++) {
        int cur = it & 1, nxt = cur ^ 1;
        bool more = (it + 1 < NIT);
        if (more) { load_A((it + 1) * KC); cp_B(nxt, (it + 1) * KC); }
        if (more) cp_wait<1>(); else cp_wait<0>();
        __syncthreads();

        uint32_t abase = smem_a + (uint32_t)(cur * 64 * SW) * 4;
        uint32_t bbase = smem_b + (uint32_t)(cur * N * SW) * 4;
#pragma unroll
        for (int kk = 0; kk < KC; kk += 8) {
            unsigned afr[MT][4];
#pragma unroll
            for (int mi = 0; mi < MT; mi++)
                ldsm4(afr[mi][0], afr[mi][1], afr[mi][2], afr[mi][3],
                      abase + (uint32_t)((wm * WM + mi * 16 + ra) * SWB + kk * 4 + ca));
            unsigned bfr[8][2];
#pragma unroll
            for (int nis = 0; nis < 8; nis += 2)
                ldsm4(bfr[nis][0], bfr[nis][1], bfr[nis + 1][0], bfr[nis + 1][1],
                      bbase + (uint32_t)((wn * 64 + nis * 8 + rb) * SWB + kk * 4 + cb));
#pragma unroll
            for (int mi = 0; mi < MT; mi++)
#pragma unroll
                for (int ni = 0; ni < 8; ni++)
                    mma8(acc[mi][ni], afr[mi], bfr[ni]);
        }
        if (more) sts_A(nxt);
        __syncthreads();
    }

    // ---- epilogue ----
    float rs[MT][2], rss[MT][2];
#pragma unroll
    for (int mi = 0; mi < MT; mi++) { rs[mi][0] = rs[mi][1] = 0.f; rss[mi][0] = rss[mi][1] = 0.f; }

#pragma unroll
    for (int mi = 0; mi < MT; mi++)
#pragma unroll
        for (int ni = 0; ni < 8; ni++)
#pragma unroll
            for (int e4 = 0; e4 < 4; e4++) {
                int h = e4 >> 1, e = e4 & 1;
                int col = wn * 64 + ni * 8 + q4 * 2 + e;
                float v = acc[mi][ni][e4] + __ldg(bias + col);
                acc[mi][ni][e4] = v;
                if (EPI == 1) { rs[mi][h] += v; rss[mi][h] += v * v; }
                if (EPI == 2) { rs[mi][h] += v * __ldg(p0 + col); rss[mi][h] += v * v; }
            }

    if (EPI == 1 || EPI == 2) {
#pragma unroll
        for (int mi = 0; mi < MT; mi++)
#pragma unroll
            for (int h = 0; h < 2; h++) {
                float s = rs[mi][h], ss = rss[mi][h];
                s  += __shfl_xor_sync(0xffffffffu, s, 1);
                s  += __shfl_xor_sync(0xffffffffu, s, 2);
                ss += __shfl_xor_sync(0xffffffffu, ss, 1);
                ss += __shfl_xor_sync(0xffffffffu, ss, 2);
                if (q4 == 0) {
                    int lr = wm * WM + mi * 16 + gid + h * 8;
                    sred[lr * WARPS_N + wn] = s; ssred[lr * WARPS_N + wn] = ss;
                }
            }
        __syncthreads();
    }

    if (EPI == 1) {
        float mu[MT][2], rstd[MT][2];
#pragma unroll
        for (int mi = 0; mi < MT; mi++)
#pragma unroll
            for (int h = 0; h < 2; h++) {
                int lr = wm * WM + mi * 16 + gid + h * 8;
                float s = 0.f, ss = 0.f;
#pragma unroll
                for (int j = 0; j < WARPS_N; j++) { s += sred[lr * WARPS_N + j]; ss += ssred[lr * WARPS_N + j]; }
                float m = s * (1.f / N);
                float var = ss * (1.f / N) - m * m;
                mu[mi][h] = m; rstd[mi][h] = rsqrtf(var + 1e-5f);
            }
#pragma unroll
        for (int mi = 0; mi < MT; mi++)
#pragma unroll
            for (int ni = 0; ni < 8; ni++) {
                int col = wn * 64 + ni * 8 + q4 * 2;
                float w0 = __ldg(p0 + col), w1 = __ldg(p0 + col + 1);
                float c0 = __ldg(p1 + col), c1 = __ldg(p1 + col + 1);
#pragma unroll
                for (int h = 0; h < 2; h++) {
                    int lr = wm * WM + mi * 16 + gid + h * 8;
                    float2 o;
                    o.x = (acc[mi][ni][h * 2 + 0] - mu[mi][h]) * rstd[mi][h] * w0 + c0;
                    o.y = (acc[mi][ni][h * 2 + 1] - mu[mi][h]) * rstd[mi][h] * w1 + c1;
                    *(float2*)(out + (size_t)(m0 + lr) * N + col) = o;
                }
            }
    }
    if (EPI == 2) {
        if (tid < 64) {
            float dot = 0.f, nsq = 0.f;
#pragma unroll
            for (int j = 0; j < WARPS_N; j++) { dot += sred[tid * WARPS_N + j]; nsq += ssred[tid * WARPS_N + j]; }
            float nq = sqrtf(nsq);
            float sim = dot / (fmaxf(nq, 1e-8f) * fmaxf(*spn, 1e-8f));
            out[m0 + tid] = fmaxf(sim, 0.f);
        }
    }
    if (EPI == 0 || EPI == 3) {
#pragma unroll
        for (int mi = 0; mi < MT; mi++)
#pragma unroll
            for (int ni = 0; ni < 8; ni++) {
                int col = wn * 64 + ni * 8 + q4 * 2;
#pragma unroll
                for (int h = 0; h < 2; h++) {
                    int lr = wm * WM + mi * 16 + gid + h * 8;
                    float vx = acc[mi][ni][h * 2 + 0], vy = acc[mi][ni][h * 2 + 1];
                    if (EPI == 3) { vx = 1.f / (1.f + expf(-vx)); vy = 1.f / (1.f + expf(-vy)); }
                    *(float2*)(out + (size_t)(m0 + lr) * N + col) = make_float2(vx, vy);
                }
            }
    }
}

// ---------------- K5: apply alpha/gate, inverse Haar, write output ----------------
__global__ void final_kernel(const float* __restrict__ xb, float* __restrict__ out)
{
    __shared__ __align__(16) float xs[8 * 128];
    int bi = blockIdx.x, c = blockIdx.y, b = blockIdx.z;
    size_t img = ((size_t)(b * C_ + c)) * H_;
    int t = threadIdx.x;
    int lrow = t >> 5, lcol = t & 31;
    ((float4*)xs)[t] = ((const float4*)(xb + (img + 8 * bi + lrow) * W_))[lcol];
    __syncthreads();
    int rp = t >> 6, j = t & 63;
    float2 top = ((const float2*)(xs + (2 * rp) * W_))[j];
    float2 bot = ((const float2*)(xs + (2 * rp + 1) * W_))[j];
    float p00 = top.x, p01 = top.y, p10 = bot.x, p11 = bot.y;
    float a  = 0.25f * (p00 + p01 + p10 + p11);
    float hb = 0.25f * (p00 - p01 + p10 - p11);
    float vb = 0.25f * (p00 + p01 - p10 - p11);
    float db = 0.25f * (p00 - p01 - p10 + p11);
    int hr = 4 * bi + rp, hc = j;
    int tok = (hr >> 1) * 32 + (hc >> 1);
    float ah = __ldg(&g_alpha[(0 * B_ + b) * TOK_HF + tok]);
    float av = __ldg(&g_alpha[(1 * B_ + b) * TOK_HF + tok]);
    float ad = __ldg(&g_alpha[(2 * B_ + b) * TOK_HF + tok]);
    int tg = (hr >> 2) * 16 + (hc >> 2);
    float gt = __ldg(&g_gate[((size_t)(b * 256 + tg)) * C_ + c]);
    float ae = a * gt, he = hb * ah, ve = vb * av, de = db * ad;
    float2 o0 = make_float2(ae + he + ve + de, ae - he + ve - de);
    float2 o1 = make_float2(ae + he - ve - de, ae - he - ve + de);
    int row0 = 8 * bi + 2 * rp;
    ((float2*)(out + (img + row0) * W_))[j] = o0;
    ((float2*)(out + (img + row0 + 1) * W_))[j] = o1;
}

static constexpr int SMEM_GEMM(int N, int WARPS_N) {
    return (2 * 64 * 20 + 2 * N * 20 + 2 * 64 * WARPS_N + 4) * 4;
}

extern "C" void kernel_launch(void* const* d_in, const int* in_sizes, int n_in,
                              void* d_out, int out_size)
{
    const float* xb      = (const float*)d_in[0];
    const float* xsm     = (const float*)d_in[1];
    const float* hf_w1   = (const float*)d_in[2];
    const float* hf_b1   = (const float*)d_in[3];
    const float* hf_ln_w = (const float*)d_in[4];
    const float* hf_ln_b = (const float*)d_in[5];
    const float* hf_w2   = (const float*)d_in[6];
    const float* hf_b2   = (const float*)d_in[7];
    const float* hf_pr   = (const float*)d_in[8];
    const float* low_w   = (const float*)d_in[9];
    const float* low_b   = (const float*)d_in[10];
    const float* lf_w1   = (const float*)d_in[11];
    const float* lf_b1   = (const float*)d_in[12];
    const float* lf_ln_w = (const float*)d_in[13];
    const float* lf_ln_b = (const float*)d_in[14];
    const float* lf_w2   = (const float*)d_in[15];
    const float* lf_b2   = (const float*)d_in[16];

    void *pz, *pps, *pH, *pHlf, *pktok, *pgate, *palpha, *pwt;
    cudaGetSymbolAddress(&pz, g_z);
    cudaGetSymbolAddress(&pps, g_ps);
    cudaGetSymbolAddress(&pH, g_H);
    cudaGetSymbolAddress(&pHlf, g_Hlf);
    cudaGetSymbolAddress(&pktok, g_ktok);
    cudaGetSymbolAddress(&pgate, g_gate);
    cudaGetSymbolAddress(&palpha, g_alpha);
    cudaGetSymbolAddress(&pwt, g_wt);
    const float* wt = (const float*)pwt;

    cudaFuncSetAttribute((const void*)gemm_kernel<256, 512, 0, 1>,
                         cudaFuncAttributeMaxDynamicSharedMemorySize, SMEM_GEMM(512, 8));
    cudaFuncSetAttribute((const void*)gemm_kernel<512, 256, 2, 2>,
                         cudaFuncAttributeMaxDynamicSharedMemorySize, SMEM_GEMM(256, 4));
    cudaFuncSetAttribute((const void*)gemm_kernel<512, 256, 1, 0>,
                         cudaFuncAttributeMaxDynamicSharedMemorySize, SMEM_GEMM(256, 4));
    cudaFuncSetAttribute((const void*)gemm_kernel<256, 512, 2, 1>,
                         cudaFuncAttributeMaxDynamicSharedMemorySize, SMEM_GEMM(512, 8));
    cudaFuncSetAttribute((const void*)gemm_kernel<512, 256, 2, 3>,
                         cudaFuncAttributeMaxDynamicSharedMemorySize, SMEM_GEMM(256, 4));

    transpose5_kernel<<<dim3(16, 16, 5), dim3(32, 8)>>>(hf_w1, hf_w2, low_w, lf_w1, lf_w2);
    haar_z_kernel<<<dim3(4, 256, 16), 256>>>(xb);
    pool_small_kernel<<<dim3(512, 16), 256>>>(xsm);

    // hf chain
    gemm_kernel<256, 512, 0, 1><<<M_HF / 64, 512, SMEM_GEMM(512, 8)>>>(
        (const float*)pz, wt + 0 * 512 * 256, hf_b1, hf_ln_w, hf_ln_b, (float*)pH);
    gemm_kernel<512, 256, 2, 2><<<M_HF / 64, 512, SMEM_GEMM(256, 4)>>>(
        (const float*)pH, wt + 1 * 512 * 256, hf_b2, hf_pr, nullptr, (float*)palpha);

    // lf chain
    gemm_kernel<512, 256, 1, 0><<<M_LF / 64, 512, SMEM_GEMM(256, 4)>>>(
        (const float*)pps, wt + 2 * 512 * 256, low_b, nullptr, nullptr, (float*)pktok);
    gemm_kernel<256, 512, 2, 1><<<M_LF / 64, 512, SMEM_GEMM(512, 8)>>>(
        (const float*)pktok, wt + 3 * 512 * 256, lf_b1, lf_ln_w, lf_ln_b, (float*)pHlf);
    gemm_kernel<512, 256, 2, 3><<<M_LF / 64, 512, SMEM_GEMM(256, 4)>>>(
        (const float*)pHlf, wt + 4 * 512 * 256, lf_b2, nullptr, nullptr, (float*)pgate);

    final_kernel<<<dim3(16, 256, 16), 256>>>(xb, (float*)d_out);
}

// round 4
// speedup vs baseline: 1.6936x; 1.0850x over previous
#include <cuda_runtime.h>
#include <cstdint>
#include <math.h>

#define DEV_INLINE __device__ __forceinline__

static constexpr int B_ = 16, C_ = 256, H_ = 128, W_ = 128;
static constexpr int CS = 512;
static constexpr int TOK_HF = 1024;
static constexpr int M_HF = 3 * B_ * TOK_HF;     // 49152
static constexpr int M_LF = B_ * 256;            // 4096

// ---------------- scratch ----------------
__device__ float g_z[3ULL * B_ * C_ * TOK_HF];       // [band][b][c][tok]
__device__ float g_ps[(size_t)B_ * CS * 256];        // [b][s][tok]
__device__ float g_H[(size_t)M_HF * 512];            // RAW hidden (hf)
__device__ float g_Hlf[(size_t)M_LF * 512];          // RAW hidden (lf)
__device__ float g_ktok[(size_t)M_LF * C_];
__device__ float g_gate[(size_t)M_LF * C_];
__device__ float g_alpha[3 * B_ * TOK_HF];
__device__ float g_wt[5ULL * 512 * 256];             // transposed weights [n][k]
__device__ float2 g_stats_hf[(size_t)M_HF * 2];      // per-row (sum, sumsq), 2 halves
__device__ float2 g_stats_lf[(size_t)M_LF * 2];
__device__ float g_c1[2 * 256];                      // LN-fold col sums (hf, lf)
__device__ float g_bp[2 * 256];                      // folded bias (hf, lf)

// ---------------- weight transpose (+ LN-weight folding for w2 mats) ----------------
__global__ void transpose5_kernel(const float* __restrict__ w0, const float* __restrict__ w1,
                                  const float* __restrict__ w2, const float* __restrict__ w3,
                                  const float* __restrict__ w4,
                                  const float* __restrict__ hf_lnw, const float* __restrict__ lf_lnw)
{
    __shared__ float tile[32][33];
    int mi = blockIdx.z;
    const float* in; int R, Cc; const float* lnw = nullptr;
    switch (mi) {
        case 0: in = w0; R = 256; Cc = 512; break;                 // hf_w1
        case 1: in = w1; R = 512; Cc = 256; lnw = hf_lnw; break;   // hf_w2 (folded)
        case 2: in = w2; R = 512; Cc = 256; break;                 // low_w
        case 3: in = w3; R = 256; Cc = 512; break;                 // lf_w1
        default: in = w4; R = 512; Cc = 256; lnw = lf_lnw; break;  // lf_w2 (folded)
    }
    float* out = g_wt + (size_t)mi * 512 * 256;
    int bx = blockIdx.x * 32, by = blockIdx.y * 32;
    if (bx >= Cc || by >= R) return;
    int tx = threadIdx.x, ty = threadIdx.y;
#pragma unroll
    for (int j = 0; j < 32; j += 8) {
        int row = by + ty + j;
        float v = in[(size_t)row * Cc + bx + tx];
        if (lnw) v *= __ldg(lnw + row);
        tile[ty + j][tx] = v;
    }
    __syncthreads();
#pragma unroll
    for (int j = 0; j < 32; j += 8)
        out[(size_t)(bx + ty + j) * R + by + tx] = tile[tx][ty + j];
}

// ---------------- fold kernel: c1[n] = sum_k W2'[n][k], bp[n] = b2[n] + sum_k lnb_k*W2[k][n]
__global__ void fold_kernel(const float* __restrict__ w2a, const float* __restrict__ lnba,
                            const float* __restrict__ b2a,
                            const float* __restrict__ w2b, const float* __restrict__ lnbb,
                            const float* __restrict__ b2b)
{
    int mi = blockIdx.x;   // 0 hf, 1 lf
    int n = threadIdx.x;
    const float* wt = g_wt + (size_t)(mi ? 4 : 1) * 512 * 256;
    const float* w2 = mi ? w2b : w2a;
    const float* lnb = mi ? lnbb : lnba;
    const float* b2 = mi ? b2b : b2a;
    float s1 = 0.f, s2 = 0.f;
    for (int k = 0; k < 512; k++) {
        s1 += wt[(size_t)n * 512 + k];
        s2 += lnb[k] * w2[(size_t)k * 256 + n];
    }
    g_c1[mi * 256 + n] = s1;
    g_bp[mi * 256 + n] = b2[n] + s2;
}

// ---------------- K1: Haar bands -> abs-pooled z tokens ----------------
__global__ void haar_z_kernel(const float* __restrict__ xb)
{
    int tid = threadIdx.x;
    int tk = blockIdx.x * 256 + tid;
    int c = blockIdx.y, b = blockIdx.z;
    int ti = tk >> 5, tj = tk & 31;
    const float* base = xb + ((size_t)(b * C_ + c) * H_ + 4 * ti) * W_ + 4 * tj;
    float4 r0 = *(const float4*)(base);
    float4 r1 = *(const float4*)(base + W_);
    float4 r2 = *(const float4*)(base + 2 * W_);
    float4 r3 = *(const float4*)(base + 3 * W_);
    float zh = 0.f, zv = 0.f, zd = 0.f;
#define HBLK(p00, p01, p10, p11) \
    zh += fabsf((p00) - (p01) + (p10) - (p11)); \
    zv += fabsf((p00) + (p01) - (p10) - (p11)); \
    zd += fabsf((p00) - (p01) - (p10) + (p11));
    HBLK(r0.x, r0.y, r1.x, r1.y)
    HBLK(r0.z, r0.w, r1.z, r1.w)
    HBLK(r2.x, r2.y, r3.x, r3.y)
    HBLK(r2.z, r2.w, r3.z, r3.w)
#undef HBLK
    const float s = 0.0625f;
    size_t base_o = ((size_t)(b) * C_ + c) * TOK_HF + tk;
    const size_t BS = (size_t)B_ * C_ * TOK_HF;
    g_z[base_o]          = zh * s;
    g_z[BS + base_o]     = zv * s;
    g_z[2 * BS + base_o] = zd * s;
}

// ---------------- K2: 4x4 mean-pool of x_small ----------------
__global__ void pool_small_kernel(const float* __restrict__ xsm)
{
    int s = blockIdx.x, b = blockIdx.y;
    const float* src = xsm + ((size_t)(b * CS + s)) * 64 * 64;
    int t = threadIdx.x;
    int tj = t & 15, ti = t >> 4;
    float sum = 0.f;
#pragma unroll
    for (int r = 0; r < 4; r++) {
        float4 v = *(const float4*)(src + (4 * ti + r) * 64 + 4 * tj);
        sum += v.x + v.y + v.z + v.w;
    }
    g_ps[((size_t)(b * CS + s)) * 256 + t] = sum * (1.f / 16.f);
}

// ---------------- asm helpers ----------------
DEV_INLINE void mma8(float* c, const unsigned* a, const unsigned* b) {
    asm volatile("mma.sync.aligned.m16n8k8.row.col.f32.tf32.tf32.f32 "
                 "{%0,%1,%2,%3}, {%4,%5,%6,%7}, {%8,%9}, {%0,%1,%2,%3};"
                 : "+f"(c[0]), "+f"(c[1]), "+f"(c[2]), "+f"(c[3])
                 : "r"(a[0]), "r"(a[1]), "r"(a[2]), "r"(a[3]),
                   "r"(b[0]), "r"(b[1]));
}
DEV_INLINE void ldsm4(unsigned& r0, unsigned& r1, unsigned& r2, unsigned& r3, uint32_t addr) {
    asm volatile("ldmatrix.sync.aligned.m8n8.x4.shared.b16 {%0,%1,%2,%3}, [%4];"
                 : "=r"(r0), "=r"(r1), "=r"(r2), "=r"(r3) : "r"(addr));
}
DEV_INLINE void cp16(uint32_t s, const void* g) {
    asm volatile("cp.async.cg.shared.global [%0], [%1], 16;" :: "r"(s), "l"(g));
}
DEV_INLINE void cp_commit() { asm volatile("cp.async.commit_group;"); }
template<int NN> DEV_INLINE void cp_wait() { asm volatile("cp.async.wait_group %0;" :: "n"(NN)); }

// ---------------- unified 64x256-tile GEMM, 256 threads, 2 CTAs/SM ----------------
// C = A(64xK) @ Bt^T (Bt stored [n][k]).  AMODE: 0 z-layout, 1 ps-layout, 2 row-major.
// EPI: 0 = bias store; 1 = bias store + partial row stats (half = blockIdx.y);
//      2 = LN-fold + cos-sim -> relu -> alpha;  3 = LN-fold + sigmoid store.
template<int K, int AMODE, int EPI, int OSTRIDE>
__global__ void __launch_bounds__(256, 2)
gemm256_kernel(const float* __restrict__ A, const float* __restrict__ Bt,
               const float* __restrict__ bias, const float* __restrict__ p0,
               float* __restrict__ out, float2* __restrict__ stats,
               const float* __restrict__ c1)
{
    constexpr int KC = 16, SW = 20, SWB = 80, NIT = K / KC, NN = 256;
    constexpr int MT = 2;

    extern __shared__ __align__(16) float dsm[];
    float* As = dsm;                    // 2 * 64 * SW
    float* Bs = As + 2 * 64 * SW;       // 3 * 256 * SW
    float* sred = Bs + 3 * NN * SW;     // 64*4
    float* ssred = sred + 256;          // 64*4
    float* spn = ssred + 256;

    int tid = threadIdx.x;
    int lane = tid & 31, warp = tid >> 5;
    int wn = warp & 3, wm = warp >> 2;  // 4 N-warps x 2 M-warps
    int gid = lane >> 2, q4 = lane & 3;
    int m0 = blockIdx.x * 64;
    int n0 = blockIdx.y * 256;

    const float* Ab; int astride = 0;
    if (AMODE == 0) { Ab = A + (size_t)(m0 >> 10) * (C_ * TOK_HF) + (m0 & 1023); astride = TOK_HF; }
    else if (AMODE == 1) { Ab = A + (size_t)(m0 >> 8) * (CS * 256) + (m0 & 255); astride = 256; }
    else { Ab = A + (size_t)m0 * K; }
    const float* BtB = Bt + (size_t)n0 * K;

    if (EPI == 2 && warp == 0) {
        float s = 0.f;
        for (int i = lane; i < 256; i += 32) { float v = p0[i]; s += v * v; }
#pragma unroll
        for (int o = 16; o; o >>= 1) s += __shfl_xor_sync(0xffffffffu, s, o);
        if (lane == 0) *spn = sqrtf(s);
    }

    uint32_t smem_a = (uint32_t)__cvta_generic_to_shared(As);
    uint32_t smem_b = (uint32_t)__cvta_generic_to_shared(Bs);

    int la_m, la_kg;
    if (AMODE <= 1) { la_m = tid & 63; la_kg = tid >> 6; }
    else            { la_m = tid >> 2; la_kg = tid & 3; }

    float areg[4];
    auto load_A = [&](int k0) {
        if (AMODE <= 1) {
#pragma unroll
            for (int i = 0; i < 4; i++)
                areg[i] = __ldg(Ab + (size_t)(k0 + la_kg * 4 + i) * astride + la_m);
        } else {
            float4 v = *(const float4*)(Ab + (size_t)la_m * K + k0 + la_kg * 4);
            areg[0] = v.x; areg[1] = v.y; areg[2] = v.z; areg[3] = v.w;
        }
    };
    auto sts_A = [&](int st) {
        *(float4*)(As + st * 64 * SW + la_m * SW + la_kg * 4) =
            make_float4(areg[0], areg[1], areg[2], areg[3]);
    };
    auto cp_B = [&](int st, int k0) {
#pragma unroll
        for (int j = 0; j < 4; j++) {
            int idx = tid + j * 256;
            int n = idx >> 2, kc = idx & 3;
            cp16(smem_b + (uint32_t)((st * NN + n) * SW + kc * 4) * 4,
                 BtB + (size_t)n * K + k0 + kc * 4);
        }
    };

    int ra = lane & 15;
    int ca = (lane & 16) ? 16 : 0;
    int rb = (lane & 7) + ((lane >> 4) << 3);
    int cb = (lane & 8) ? 16 : 0;

    float acc[MT][8][4];
#pragma unroll
    for (int mi = 0; mi < MT; mi++)
#pragma unroll
        for (int ni = 0; ni < 8; ni++)
#pragma unroll
            for (int e = 0; e < 4; e++) acc[mi][ni][e] = 0.f;

    // prologue: A stage 0, B stages 0 and 1
    load_A(0); sts_A(0);
    cp_B(0, 0); cp_commit();
    if (NIT > 1) { cp_B(1, KC); cp_commit(); }

    for (int it = 0; it < NIT; it++) {
        int curA = it & 1, curB = it % 3;
        bool more = (it + 1 < NIT);
        if (more) load_A((it + 1) * KC);
        if (it + 2 < NIT) { cp_B((it + 2) % 3, (it + 2) * KC); cp_commit(); cp_wait<2>(); }
        else if (it + 1 < NIT) cp_wait<1>();
        else cp_wait<0>();
        __syncthreads();

        uint32_t abase = smem_a + (uint32_t)(curA * 64 * SW) * 4;
        uint32_t bbase = smem_b + (uint32_t)(curB * NN * SW) * 4;
#pragma unroll
        for (int kk = 0; kk < KC; kk += 8) {
            unsigned afr[MT][4];
#pragma unroll
            for (int mi = 0; mi < MT; mi++)
                ldsm4(afr[mi][0], afr[mi][1], afr[mi][2], afr[mi][3],
                      abase + (uint32_t)((wm * 32 + mi * 16 + ra) * SWB + kk * 4 + ca));
            unsigned bfr[8][2];
#pragma unroll
            for (int nis = 0; nis < 8; nis += 2)
                ldsm4(bfr[nis][0], bfr[nis][1], bfr[nis + 1][0], bfr[nis + 1][1],
                      bbase + (uint32_t)((wn * 64 + nis * 8 + rb) * SWB + kk * 4 + cb));
#pragma unroll
            for (int mi = 0; mi < MT; mi++)
#pragma unroll
                for (int ni = 0; ni < 8; ni++)
                    mma8(acc[mi][ni], afr[mi], bfr[ni]);
        }
        if (more) sts_A(curA ^ 1);
        __syncthreads();
    }

    // ---- epilogue ----
    float mu_rs[MT][2], rstd_v[MT][2];
    if (EPI == 2 || EPI == 3) {
#pragma unroll
        for (int mi = 0; mi < MT; mi++)
#pragma unroll
            for (int h = 0; h < 2; h++) {
                int lr = wm * 32 + mi * 16 + gid + h * 8;
                float2 s0 = stats[(size_t)(m0 + lr) * 2 + 0];
                float2 s1 = stats[(size_t)(m0 + lr) * 2 + 1];
                float sum = s0.x + s1.x, ss = s0.y + s1.y;
                float mu = sum * (1.f / 512.f);
                float var = ss * (1.f / 512.f) - mu * mu;
                float rstd = rsqrtf(var + 1e-5f);
                rstd_v[mi][h] = rstd;
                mu_rs[mi][h] = mu * rstd;
            }
    }

    float rs[MT][2], rss[MT][2];
#pragma unroll
    for (int mi = 0; mi < MT; mi++) { rs[mi][0] = rs[mi][1] = 0.f; rss[mi][0] = rss[mi][1] = 0.f; }

#pragma unroll
    for (int mi = 0; mi < MT; mi++)
#pragma unroll
        for (int ni = 0; ni < 8; ni++)
#pragma unroll
            for (int e4 = 0; e4 < 4; e4++) {
                int h = e4 >> 1, e = e4 & 1;
                int col = wn * 64 + ni * 8 + q4 * 2 + e;
                float v;
                if (EPI <= 1) {
                    v = acc[mi][ni][e4] + __ldg(bias + n0 + col);
                    if (EPI == 1) { rs[mi][h] += v; rss[mi][h] += v * v; }
                } else {
                    v = rstd_v[mi][h] * acc[mi][ni][e4] - mu_rs[mi][h] * __ldg(c1 + col)
                        + __ldg(bias + col);
                    if (EPI == 2) { rs[mi][h] += v * __ldg(p0 + col); rss[mi][h] += v * v; }
                }
                acc[mi][ni][e4] = v;
            }

    if (EPI == 1 || EPI == 2) {
#pragma unroll
        for (int mi = 0; mi < MT; mi++)
#pragma unroll
            for (int h = 0; h < 2; h++) {
                float s = rs[mi][h], ss = rss[mi][h];
                s  += __shfl_xor_sync(0xffffffffu, s, 1);
                s  += __shfl_xor_sync(0xffffffffu, s, 2);
                ss += __shfl_xor_sync(0xffffffffu, ss, 1);
                ss += __shfl_xor_sync(0xffffffffu, ss, 2);
                if (q4 == 0) {
                    int lr = wm * 32 + mi * 16 + gid + h * 8;
                    sred[lr * 4 + wn] = s; ssred[lr * 4 + wn] = ss;
                }
            }
        __syncthreads();
    }

    if (EPI == 0 || EPI == 1 || EPI == 3) {
#pragma unroll
        for (int mi = 0; mi < MT; mi++)
#pragma unroll
            for (int ni = 0; ni < 8; ni++) {
                int col = wn * 64 + ni * 8 + q4 * 2;
#pragma unroll
                for (int h = 0; h < 2; h++) {
                    int lr = wm * 32 + mi * 16 + gid + h * 8;
                    float vx = acc[mi][ni][h * 2 + 0], vy = acc[mi][ni][h * 2 + 1];
                    if (EPI == 3) { vx = 1.f / (1.f + expf(-vx)); vy = 1.f / (1.f + expf(-vy)); }
                    *(float2*)(out + (size_t)(m0 + lr) * OSTRIDE + n0 + col) = make_float2(vx, vy);
                }
            }
    }
    if (EPI == 1) {
        if (tid < 64) {
            float s = 0.f, ss = 0.f;
#pragma unroll
            for (int j = 0; j < 4; j++) { s += sred[tid * 4 + j]; ss += ssred[tid * 4 + j]; }
            stats[(size_t)(m0 + tid) * 2 + blockIdx.y] = make_float2(s, ss);
        }
    }
    if (EPI == 2) {
        if (tid < 64) {
            float dot = 0.f, nsq = 0.f;
#pragma unroll
            for (int j = 0; j < 4; j++) { dot += sred[tid * 4 + j]; nsq += ssred[tid * 4 + j]; }
            float nq = sqrtf(nsq);
            float sim = dot / (fmaxf(nq, 1e-8f) * fmaxf(*spn, 1e-8f));
            out[m0 + tid] = fmaxf(sim, 0.f);
        }
    }
}

// ---------------- K5: apply alpha/gate, inverse Haar, write output ----------------
__global__ void final_kernel(const float* __restrict__ xb, float* __restrict__ out)
{
    __shared__ __align__(16) float xs[8 * 128];
    int bi = blockIdx.x, c = blockIdx.y, b = blockIdx.z;
    size_t img = ((size_t)(b * C_ + c)) * H_;
    int t = threadIdx.x;
    int lrow = t >> 5, lcol = t & 31;
    ((float4*)xs)[t] = ((const float4*)(xb + (img + 8 * bi + lrow) * W_))[lcol];
    __syncthreads();
    int rp = t >> 6, j = t & 63;
    float2 top = ((const float2*)(xs + (2 * rp) * W_))[j];
    float2 bot = ((const float2*)(xs + (2 * rp + 1) * W_))[j];
    float p00 = top.x, p01 = top.y, p10 = bot.x, p11 = bot.y;
    float a  = 0.25f * (p00 + p01 + p10 + p11);
    float hb = 0.25f * (p00 - p01 + p10 - p11);
    float vb = 0.25f * (p00 + p01 - p10 - p11);
    float db = 0.25f * (p00 - p01 - p10 + p11);
    int hr = 4 * bi + rp, hc = j;
    int tok = (hr >> 1) * 32 + (hc >> 1);
    float ah = __ldg(&g_alpha[(0 * B_ + b) * TOK_HF + tok]);
    float av = __ldg(&g_alpha[(1 * B_ + b) * TOK_HF + tok]);
    float ad = __ldg(&g_alpha[(2 * B_ + b) * TOK_HF + tok]);
    int tg = (hr >> 2) * 16 + (hc >> 2);
    float gt = __ldg(&g_gate[((size_t)(b * 256 + tg)) * C_ + c]);
    float ae = a * gt, he = hb * ah, ve = vb * av, de = db * ad;
    float2 o0 = make_float2(ae + he + ve + de, ae - he + ve - de);
    float2 o1 = make_float2(ae + he - ve - de, ae - he - ve + de);
    int row0 = 8 * bi + 2 * rp;
    ((float2*)(out + (img + row0) * W_))[j] = o0;
    ((float2*)(out + (img + row0 + 1) * W_))[j] = o1;
}

static constexpr int SMEM_G = (2 * 64 * 20 + 3 * 256 * 20 + 512 + 4) * 4;  // ~74 KB

extern "C" void kernel_launch(void* const* d_in, const int* in_sizes, int n_in,
                              void* d_out, int out_size)
{
    const float* xb      = (const float*)d_in[0];
    const float* xsm     = (const float*)d_in[1];
    const float* hf_w1   = (const float*)d_in[2];
    const float* hf_b1   = (const float*)d_in[3];
    const float* hf_ln_w = (const float*)d_in[4];
    const float* hf_ln_b = (const float*)d_in[5];
    const float* hf_w2   = (const float*)d_in[6];
    const float* hf_b2   = (const float*)d_in[7];
    const float* hf_pr   = (const float*)d_in[8];
    const float* low_w   = (const float*)d_in[9];
    const float* low_b   = (const float*)d_in[10];
    const float* lf_w1   = (const float*)d_in[11];
    const float* lf_b1   = (const float*)d_in[12];
    const float* lf_ln_w = (const float*)d_in[13];
    const float* lf_ln_b = (const float*)d_in[14];
    const float* lf_w2   = (const float*)d_in[15];
    const float* lf_b2   = (const float*)d_in[16];

    void *pz, *pps, *pH, *pHlf, *pktok, *pgate, *palpha, *pwt, *psh, *psl, *pc1, *pbp;
    cudaGetSymbolAddress(&pz, g_z);
    cudaGetSymbolAddress(&pps, g_ps);
    cudaGetSymbolAddress(&pH, g_H);
    cudaGetSymbolAddress(&pHlf, g_Hlf);
    cudaGetSymbolAddress(&pktok, g_ktok);
    cudaGetSymbolAddress(&pgate, g_gate);
    cudaGetSymbolAddress(&palpha, g_alpha);
    cudaGetSymbolAddress(&pwt, g_wt);
    cudaGetSymbolAddress(&psh, g_stats_hf);
    cudaGetSymbolAddress(&psl, g_stats_lf);
    cudaGetSymbolAddress(&pc1, g_c1);
    cudaGetSymbolAddress(&pbp, g_bp);
    const float* wt = (const float*)pwt;
    float2* sh = (float2*)psh;
    float2* sl = (float2*)psl;
    const float* c1 = (const float*)pc1;
    const float* bp = (const float*)pbp;

    cudaFuncSetAttribute((const void*)gemm256_kernel<256, 0, 1, 512>,
                         cudaFuncAttributeMaxDynamicSharedMemorySize, SMEM_G);
    cudaFuncSetAttribute((const void*)gemm256_kernel<512, 2, 2, 256>,
                         cudaFuncAttributeMaxDynamicSharedMemorySize, SMEM_G);
    cudaFuncSetAttribute((const void*)gemm256_kernel<512, 1, 0, 256>,
                         cudaFuncAttributeMaxDynamicSharedMemorySize, SMEM_G);
    cudaFuncSetAttribute((const void*)gemm256_kernel<256, 2, 1, 512>,
                         cudaFuncAttributeMaxDynamicSharedMemorySize, SMEM_G);
    cudaFuncSetAttribute((const void*)gemm256_kernel<512, 2, 3, 256>,
                         cudaFuncAttributeMaxDynamicSharedMemorySize, SMEM_G);

    transpose5_kernel<<<dim3(16, 16, 5), dim3(32, 8)>>>(hf_w1, hf_w2, low_w, lf_w1, lf_w2,
                                                        hf_ln_w, lf_ln_w);
    fold_kernel<<<2, 256>>>(hf_w2, hf_ln_b, hf_b2, lf_w2, lf_ln_b, lf_b2);
    haar_z_kernel<<<dim3(4, 256, 16), 256>>>(xb);
    pool_small_kernel<<<dim3(512, 16), 256>>>(xsm);

    // hf chain: raw hidden + stats, then LN-folded GEMM2 -> alpha
    gemm256_kernel<256, 0, 1, 512><<<dim3(M_HF / 64, 2), 256, SMEM_G>>>(
        (const float*)pz, wt + 0 * 512 * 256, hf_b1, nullptr, (float*)pH, sh, nullptr);
    gemm256_kernel<512, 2, 2, 256><<<dim3(M_HF / 64, 1), 256, SMEM_G>>>(
        (const float*)pH, wt + 1 * 512 * 256, bp + 0, hf_pr, (float*)palpha, sh, c1 + 0);

    // lf chain
    gemm256_kernel<512, 1, 0, 256><<<dim3(M_LF / 64, 1), 256, SMEM_G>>>(
        (const float*)pps, wt + 2 * 512 * 256, low_b, nullptr, (float*)pktok, nullptr, nullptr);
    gemm256_kernel<256, 2, 1, 512><<<dim3(M_LF / 64, 2), 256, SMEM_G>>>(
        (const float*)pktok, wt + 3 * 512 * 256, lf_b1, nullptr, (float*)pHlf, sl, nullptr);
    gemm256_kernel<512, 2, 3, 256><<<dim3(M_LF / 64, 1), 256, SMEM_G>>>(
        (const float*)pHlf, wt + 4 * 512 * 256, bp + 256, nullptr, (float*)pgate, sl, c1 + 256);

    final_kernel<<<dim3(16, 256, 16), 256>>>(xb, (float*)d_out);
}

// round 6
// speedup vs baseline: 1.8060x; 1.0664x over previous
#include <cuda_runtime.h>
#include <cstdint>
#include <math.h>

#define DEV_INLINE __device__ __forceinline__

static constexpr int B_ = 16, C_ = 256, H_ = 128, W_ = 128;
static constexpr int CS = 512;
static constexpr int TOK_HF = 1024;
static constexpr int M_HF = 3 * B_ * TOK_HF;     // 49152
static constexpr int M_LF = B_ * 256;            // 4096

// ---------------- scratch ----------------
__device__ float g_z[3ULL * B_ * C_ * TOK_HF];       // [band][b][c][tok]
__device__ float g_ps[(size_t)B_ * CS * 256];        // [b][s][tok]
__device__ float g_H[(size_t)M_HF * 512];            // RAW hidden (hf)
__device__ float g_Hlf[(size_t)M_LF * 512];          // RAW hidden (lf)
__device__ float g_ktok[(size_t)M_LF * C_];
__device__ float g_gate[(size_t)M_LF * C_];
__device__ float g_alpha[3 * B_ * TOK_HF];
__device__ float g_wt[5ULL * 512 * 256];             // transposed weights [n][k]
__device__ float2 g_stats_hf[(size_t)M_HF * 2];      // per-row (sum, sumsq), 2 halves
__device__ float2 g_stats_lf[(size_t)M_LF * 2];
__device__ float g_c1[2 * 256];
__device__ float g_bp[2 * 256];

// ---------------- weight transpose (+ LN-weight folding for w2 mats) ----------------
__global__ void transpose5_kernel(const float* __restrict__ w0, const float* __restrict__ w1,
                                  const float* __restrict__ w2, const float* __restrict__ w3,
                                  const float* __restrict__ w4,
                                  const float* __restrict__ hf_lnw, const float* __restrict__ lf_lnw)
{
    __shared__ float tile[32][33];
    int mi = blockIdx.z;
    const float* in; int R, Cc; const float* lnw = nullptr;
    switch (mi) {
        case 0: in = w0; R = 256; Cc = 512; break;
        case 1: in = w1; R = 512; Cc = 256; lnw = hf_lnw; break;
        case 2: in = w2; R = 512; Cc = 256; break;
        case 3: in = w3; R = 256; Cc = 512; break;
        default: in = w4; R = 512; Cc = 256; lnw = lf_lnw; break;
    }
    float* out = g_wt + (size_t)mi * 512 * 256;
    int bx = blockIdx.x * 32, by = blockIdx.y * 32;
    if (bx >= Cc || by >= R) return;
    int tx = threadIdx.x, ty = threadIdx.y;
#pragma unroll
    for (int j = 0; j < 32; j += 8) {
        int row = by + ty + j;
        float v = in[(size_t)row * Cc + bx + tx];
        if (lnw) v *= __ldg(lnw + row);
        tile[ty + j][tx] = v;
    }
    __syncthreads();
#pragma unroll
    for (int j = 0; j < 32; j += 8)
        out[(size_t)(bx + ty + j) * R + by + tx] = tile[tx][ty + j];
}

__global__ void fold_kernel(const float* __restrict__ w2a, const float* __restrict__ lnba,
                            const float* __restrict__ b2a,
                            const float* __restrict__ w2b, const float* __restrict__ lnbb,
                            const float* __restrict__ b2b)
{
    int mi = blockIdx.x;
    int n = threadIdx.x;
    const float* wt = g_wt + (size_t)(mi ? 4 : 1) * 512 * 256;
    const float* w2 = mi ? w2b : w2a;
    const float* lnb = mi ? lnbb : lnba;
    const float* b2 = mi ? b2b : b2a;
    float s1 = 0.f, s2 = 0.f;
    for (int k = 0; k < 512; k++) {
        s1 += wt[(size_t)n * 512 + k];
        s2 += lnb[k] * w2[(size_t)k * 256 + n];
    }
    g_c1[mi * 256 + n] = s1;
    g_bp[mi * 256 + n] = b2[n] + s2;
}

// ---------------- K1: Haar bands -> abs-pooled z tokens ----------------
__global__ void haar_z_kernel(const float* __restrict__ xb)
{
    int tid = threadIdx.x;
    int tk = blockIdx.x * 256 + tid;
    int c = blockIdx.y, b = blockIdx.z;
    int ti = tk >> 5, tj = tk & 31;
    const float* base = xb + ((size_t)(b * C_ + c) * H_ + 4 * ti) * W_ + 4 * tj;
    float4 r0 = *(const float4*)(base);
    float4 r1 = *(const float4*)(base + W_);
    float4 r2 = *(const float4*)(base + 2 * W_);
    float4 r3 = *(const float4*)(base + 3 * W_);
    float zh = 0.f, zv = 0.f, zd = 0.f;
#define HBLK(p00, p01, p10, p11) \
    zh += fabsf((p00) - (p01) + (p10) - (p11)); \
    zv += fabsf((p00) + (p01) - (p10) - (p11)); \
    zd += fabsf((p00) - (p01) - (p10) + (p11));
    HBLK(r0.x, r0.y, r1.x, r1.y)
    HBLK(r0.z, r0.w, r1.z, r1.w)
    HBLK(r2.x, r2.y, r3.x, r3.y)
    HBLK(r2.z, r2.w, r3.z, r3.w)
#undef HBLK
    const float s = 0.0625f;
    size_t base_o = ((size_t)(b) * C_ + c) * TOK_HF + tk;
    const size_t BS = (size_t)B_ * C_ * TOK_HF;
    g_z[base_o]          = zh * s;
    g_z[BS + base_o]     = zv * s;
    g_z[2 * BS + base_o] = zd * s;
}

// ---------------- K2: 4x4 mean-pool of x_small ----------------
__global__ void pool_small_kernel(const float* __restrict__ xsm)
{
    int s = blockIdx.x, b = blockIdx.y;
    const float* src = xsm + ((size_t)(b * CS + s)) * 64 * 64;
    int t = threadIdx.x;
    int tj = t & 15, ti = t >> 4;
    float sum = 0.f;
#pragma unroll
    for (int r = 0; r < 4; r++) {
        float4 v = *(const float4*)(src + (4 * ti + r) * 64 + 4 * tj);
        sum += v.x + v.y + v.z + v.w;
    }
    g_ps[((size_t)(b * CS + s)) * 256 + t] = sum * (1.f / 16.f);
}

// ---------------- asm helpers ----------------
DEV_INLINE void mma8(float* c, const unsigned* a, const unsigned* b) {
    asm volatile("mma.sync.aligned.m16n8k8.row.col.f32.tf32.tf32.f32 "
                 "{%0,%1,%2,%3}, {%4,%5,%6,%7}, {%8,%9}, {%0,%1,%2,%3};"
                 : "+f"(c[0]), "+f"(c[1]), "+f"(c[2]), "+f"(c[3])
                 : "r"(a[0]), "r"(a[1]), "r"(a[2]), "r"(a[3]),
                   "r"(b[0]), "r"(b[1]));
}
DEV_INLINE void ldsm4(unsigned& r0, unsigned& r1, unsigned& r2, unsigned& r3, uint32_t addr) {
    asm volatile("ldmatrix.sync.aligned.m8n8.x4.shared.b16 {%0,%1,%2,%3}, [%4];"
                 : "=r"(r0), "=r"(r1), "=r"(r2), "=r"(r3) : "r"(addr));
}
DEV_INLINE void cp16(uint32_t s, const void* g) {
    asm volatile("cp.async.cg.shared.global [%0], [%1], 16;" :: "r"(s), "l"(g));
}
DEV_INLINE void cp_commit() { asm volatile("cp.async.commit_group;"); }
template<int NN> DEV_INLINE void cp_wait() { asm volatile("cp.async.wait_group %0;" :: "n"(NN)); }

// ---------------- unified 64x256-tile GEMM, 256 threads, 2 CTAs/SM ----------------
// KC=32, double-buffered A+B, ONE __syncthreads per iteration.
// RACE-FIX vs R5: prefetch of stage nxt is issued AFTER the barrier that retires
// the previous iteration's readers of stage nxt. Overlap with compute preserved
// (waited on only at the next iteration's cp_wait).
template<int K, int AMODE, int EPI, int OSTRIDE>
__global__ void __launch_bounds__(256, 2)
gemm256_kernel(const float* __restrict__ A, const float* __restrict__ Bt,
               const float* __restrict__ bias, const float* __restrict__ p0,
               float* __restrict__ out, float2* __restrict__ stats,
               const float* __restrict__ c1)
{
    constexpr int KC = 32, SW = 36, SWB = SW * 4, NIT = K / KC, NN = 256;
    constexpr int MT = 2;

    extern __shared__ __align__(16) float dsm[];
    float* As = dsm;                    // 2 * 64 * SW
    float* Bs = As + 2 * 64 * SW;       // 2 * 256 * SW
    float* sred = Bs + 2 * NN * SW;
    float* ssred = sred + 256;
    float* spn = ssred + 256;

    int tid = threadIdx.x;
    int lane = tid & 31, warp = tid >> 5;
    int wn = warp & 3, wm = warp >> 2;
    int gid = lane >> 2, q4 = lane & 3;
    int m0 = blockIdx.x * 64;
    int n0 = blockIdx.y * 256;

    const float* Ab; int astride = 0;
    if (AMODE == 0) { Ab = A + (size_t)(m0 >> 10) * (C_ * TOK_HF) + (m0 & 1023); astride = TOK_HF; }
    else if (AMODE == 1) { Ab = A + (size_t)(m0 >> 8) * (CS * 256) + (m0 & 255); astride = 256; }
    else { Ab = A + (size_t)m0 * K; }
    const float* BtB = Bt + (size_t)n0 * K;

    if (EPI == 2 && warp == 0) {
        float s = 0.f;
        for (int i = lane; i < 256; i += 32) { float v = p0[i]; s += v * v; }
#pragma unroll
        for (int o = 16; o; o >>= 1) s += __shfl_xor_sync(0xffffffffu, s, o);
        if (lane == 0) *spn = sqrtf(s);
    }

    uint32_t smem_a = (uint32_t)__cvta_generic_to_shared(As);
    uint32_t smem_b = (uint32_t)__cvta_generic_to_shared(Bs);

    int la_m = tid & 63, la_kg = tid >> 6;
    float areg[8];
    auto load_A = [&](int k0) {
        if (AMODE <= 1) {
#pragma unroll
            for (int i = 0; i < 8; i++)
                areg[i] = __ldg(Ab + (size_t)(k0 + la_kg * 8 + i) * astride + la_m);
        }
    };
    auto sts_A = [&](int st) {
        if (AMODE <= 1) {
            float* p = As + st * 64 * SW + la_m * SW + la_kg * 8;
            *(float4*)(p)     = make_float4(areg[0], areg[1], areg[2], areg[3]);
            *(float4*)(p + 4) = make_float4(areg[4], areg[5], areg[6], areg[7]);
        }
    };
    auto cp_stage = [&](int st, int k0) {
        if (AMODE == 2) {
#pragma unroll
            for (int j = 0; j < 2; j++) {
                int idx = tid + j * 256;
                int m = idx >> 3, kq = idx & 7;
                cp16(smem_a + (uint32_t)((st * 64 + m) * SW + kq * 4) * 4,
                     Ab + (size_t)m * K + k0 + kq * 4);
            }
        }
#pragma unroll
        for (int j = 0; j < 8; j++) {
            int idx = tid + j * 256;
            int n = idx >> 3, kc = idx & 7;
            cp16(smem_b + (uint32_t)((st * NN + n) * SW + kc * 4) * 4,
                 BtB + (size_t)n * K + k0 + kc * 4);
        }
        cp_commit();
    };

    int ra = lane & 15;
    int ca = (lane & 16) ? 16 : 0;
    int rb = (lane & 7) + ((lane >> 4) << 3);
    int cb = (lane & 8) ? 16 : 0;

    float acc[MT][8][4];
#pragma unroll
    for (int mi = 0; mi < MT; mi++)
#pragma unroll
        for (int ni = 0; ni < 8; ni++)
#pragma unroll
            for (int e = 0; e < 4; e++) acc[mi][ni][e] = 0.f;

    // prologue: stage 0 fully staged; A regs for stage 1 pre-loaded
    load_A(0);
    cp_stage(0, 0);
    sts_A(0);
    if (NIT > 1) load_A(KC);

    for (int it = 0; it < NIT; it++) {
        int cur = it & 1;
        bool more = (it + 1 < NIT);
        cp_wait<0>();                 // stage cur's cp.async complete
        __syncthreads();              // publish stage cur; retire prev readers of nxt
        if (more) {
            cp_stage(cur ^ 1, (it + 1) * KC);   // safe: prev readers retired above
            sts_A(cur ^ 1);                     // published by next iteration's barrier
        }
        if (it + 2 < NIT) load_A((it + 2) * KC);

        uint32_t abase = smem_a + (uint32_t)(cur * 64 * SW) * 4;
        uint32_t bbase = smem_b + (uint32_t)(cur * NN * SW) * 4;
#pragma unroll
        for (int kk = 0; kk < KC; kk += 8) {
            unsigned afr[MT][4];
#pragma unroll
            for (int mi = 0; mi < MT; mi++)
                ldsm4(afr[mi][0], afr[mi][1], afr[mi][2], afr[mi][3],
                      abase + (uint32_t)((wm * 32 + mi * 16 + ra) * SWB + kk * 4 + ca));
            unsigned bfr[8][2];
#pragma unroll
            for (int nis = 0; nis < 8; nis += 2)
                ldsm4(bfr[nis][0], bfr[nis][1], bfr[nis + 1][0], bfr[nis + 1][1],
                      bbase + (uint32_t)((wn * 64 + nis * 8 + rb) * SWB + kk * 4 + cb));
#pragma unroll
            for (int mi = 0; mi < MT; mi++)
#pragma unroll
                for (int ni = 0; ni < 8; ni++)
                    mma8(acc[mi][ni], afr[mi], bfr[ni]);
        }
    }

    // ---- epilogue ----
    float mu_rs[MT][2], rstd_v[MT][2];
    if (EPI == 2 || EPI == 3) {
#pragma unroll
        for (int mi = 0; mi < MT; mi++)
#pragma unroll
            for (int h = 0; h < 2; h++) {
                int lr = wm * 32 + mi * 16 + gid + h * 8;
                float2 s0 = stats[(size_t)(m0 + lr) * 2 + 0];
                float2 s1 = stats[(size_t)(m0 + lr) * 2 + 1];
                float sum = s0.x + s1.x, ss = s0.y + s1.y;
                float mu = sum * (1.f / 512.f);
                float var = ss * (1.f / 512.f) - mu * mu;
                float rstd = rsqrtf(var + 1e-5f);
                rstd_v[mi][h] = rstd;
                mu_rs[mi][h] = mu * rstd;
            }
    }

    float rs[MT][2], rss[MT][2];
#pragma unroll
    for (int mi = 0; mi < MT; mi++) { rs[mi][0] = rs[mi][1] = 0.f; rss[mi][0] = rss[mi][1] = 0.f; }

#pragma unroll
    for (int mi = 0; mi < MT; mi++)
#pragma unroll
        for (int ni = 0; ni < 8; ni++)
#pragma unroll
            for (int e4 = 0; e4 < 4; e4++) {
                int h = e4 >> 1, e = e4 & 1;
                int col = wn * 64 + ni * 8 + q4 * 2 + e;
                float v;
                if (EPI <= 1) {
                    v = acc[mi][ni][e4] + __ldg(bias + n0 + col);
                    if (EPI == 1) { rs[mi][h] += v; rss[mi][h] += v * v; }
                } else {
                    v = rstd_v[mi][h] * acc[mi][ni][e4] - mu_rs[mi][h] * __ldg(c1 + col)
                        + __ldg(bias + col);
                    if (EPI == 2) { rs[mi][h] += v * __ldg(p0 + col); rss[mi][h] += v * v; }
                }
                acc[mi][ni][e4] = v;
            }

    if (EPI == 1 || EPI == 2) {
#pragma unroll
        for (int mi = 0; mi < MT; mi++)
#pragma unroll
            for (int h = 0; h < 2; h++) {
                float s = rs[mi][h], ss = rss[mi][h];
                s  += __shfl_xor_sync(0xffffffffu, s, 1);
                s  += __shfl_xor_sync(0xffffffffu, s, 2);
                ss += __shfl_xor_sync(0xffffffffu, ss, 1);
                ss += __shfl_xor_sync(0xffffffffu, ss, 2);
                if (q4 == 0) {
                    int lr = wm * 32 + mi * 16 + gid + h * 8;
                    sred[lr * 4 + wn] = s; ssred[lr * 4 + wn] = ss;
                }
            }
        __syncthreads();
    }

    if (EPI == 0 || EPI == 1 || EPI == 3) {
#pragma unroll
        for (int mi = 0; mi < MT; mi++)
#pragma unroll
            for (int ni = 0; ni < 8; ni++) {
                int col = wn * 64 + ni * 8 + q4 * 2;
#pragma unroll
                for (int h = 0; h < 2; h++) {
                    int lr = wm * 32 + mi * 16 + gid + h * 8;
                    float vx = acc[mi][ni][h * 2 + 0], vy = acc[mi][ni][h * 2 + 1];
                    if (EPI == 3) { vx = 1.f / (1.f + expf(-vx)); vy = 1.f / (1.f + expf(-vy)); }
                    *(float2*)(out + (size_t)(m0 + lr) * OSTRIDE + n0 + col) = make_float2(vx, vy);
                }
            }
    }
    if (EPI == 1) {
        if (tid < 64) {
            float s = 0.f, ss = 0.f;
#pragma unroll
            for (int j = 0; j < 4; j++) { s += sred[tid * 4 + j]; ss += ssred[tid * 4 + j]; }
            stats[(size_t)(m0 + tid) * 2 + blockIdx.y] = make_float2(s, ss);
        }
    }
    if (EPI == 2) {
        if (tid < 64) {
            float dot = 0.f, nsq = 0.f;
#pragma unroll
            for (int j = 0; j < 4; j++) { dot += sred[tid * 4 + j]; nsq += ssred[tid * 4 + j]; }
            float nq = sqrtf(nsq);
            float sim = dot / (fmaxf(nq, 1e-8f) * fmaxf(*spn, 1e-8f));
            out[m0 + tid] = fmaxf(sim, 0.f);
        }
    }
}

// ---------------- K5: apply alpha/gate, inverse Haar, write output ----------------
__global__ void final_kernel(const float* __restrict__ xb, float* __restrict__ out)
{
    __shared__ __align__(16) float xs[8 * 128];
    int bi = blockIdx.x, c = blockIdx.y, b = blockIdx.z;
    size_t img = ((size_t)(b * C_ + c)) * H_;
    int t = threadIdx.x;
    int lrow = t >> 5, lcol = t & 31;
    ((float4*)xs)[t] = ((const float4*)(xb + (img + 8 * bi + lrow) * W_))[lcol];
    __syncthreads();
    int rp = t >> 6, j = t & 63;
    float2 top = ((const float2*)(xs + (2 * rp) * W_))[j];
    float2 bot = ((const float2*)(xs + (2 * rp + 1) * W_))[j];
    float p00 = top.x, p01 = top.y, p10 = bot.x, p11 = bot.y;
    float a  = 0.25f * (p00 + p01 + p10 + p11);
    float hb = 0.25f * (p00 - p01 + p10 - p11);
    float vb = 0.25f * (p00 + p01 - p10 - p11);
    float db = 0.25f * (p00 - p01 - p10 + p11);
    int hr = 4 * bi + rp, hc = j;
    int tok = (hr >> 1) * 32 + (hc >> 1);
    float ah = __ldg(&g_alpha[(0 * B_ + b) * TOK_HF + tok]);
    float av = __ldg(&g_alpha[(1 * B_ + b) * TOK_HF + tok]);
    float ad = __ldg(&g_alpha[(2 * B_ + b) * TOK_HF + tok]);
    int tg = (hr >> 2) * 16 + (hc >> 2);
    float gt = __ldg(&g_gate[((size_t)(b * 256 + tg)) * C_ + c]);
    float ae = a * gt, he = hb * ah, ve = vb * av, de = db * ad;
    float2 o0 = make_float2(ae + he + ve + de, ae - he + ve - de);
    float2 o1 = make_float2(ae + he - ve - de, ae - he - ve + de);
    int row0 = 8 * bi + 2 * rp;
    ((float2*)(out + (img + row0) * W_))[j] = o0;
    ((float2*)(out + (img + row0 + 1) * W_))[j] = o1;
}

static constexpr int SMEM_G = (2 * 64 * 36 + 2 * 256 * 36 + 512 + 4) * 4;  // ~92 KB

extern "C" void kernel_launch(void* const* d_in, const int* in_sizes, int n_in,
                              void* d_out, int out_size)
{
    const float* xb      = (const float*)d_in[0];
    const float* xsm     = (const float*)d_in[1];
    const float* hf_w1   = (const float*)d_in[2];
    const float* hf_b1   = (const float*)d_in[3];
    const float* hf_ln_w = (const float*)d_in[4];
    const float* hf_ln_b = (const float*)d_in[5];
    const float* hf_w2   = (const float*)d_in[6];
    const float* hf_b2   = (const float*)d_in[7];
    const float* hf_pr   = (const float*)d_in[8];
    const float* low_w   = (const float*)d_in[9];
    const float* low_b   = (const float*)d_in[10];
    const float* lf_w1   = (const float*)d_in[11];
    const float* lf_b1   = (const float*)d_in[12];
    const float* lf_ln_w = (const float*)d_in[13];
    const float* lf_ln_b = (const float*)d_in[14];
    const float* lf_w2   = (const float*)d_in[15];
    const float* lf_b2   = (const float*)d_in[16];

    void *pz, *pps, *pH, *pHlf, *pktok, *pgate, *palpha, *pwt, *psh, *psl, *pc1, *pbp;
    cudaGetSymbolAddress(&pz, g_z);
    cudaGetSymbolAddress(&pps, g_ps);
    cudaGetSymbolAddress(&pH, g_H);
    cudaGetSymbolAddress(&pHlf, g_Hlf);
    cudaGetSymbolAddress(&pktok, g_ktok);
    cudaGetSymbolAddress(&pgate, g_gate);
    cudaGetSymbolAddress(&palpha, g_alpha);
    cudaGetSymbolAddress(&pwt, g_wt);
    cudaGetSymbolAddress(&psh, g_stats_hf);
    cudaGetSymbolAddress(&psl, g_stats_lf);
    cudaGetSymbolAddress(&pc1, g_c1);
    cudaGetSymbolAddress(&pbp, g_bp);
    const float* wt = (const float*)pwt;
    float2* sh = (float2*)psh;
    float2* sl = (float2*)psl;
    const float* c1 = (const float*)pc1;
    const float* bp = (const float*)pbp;

    cudaFuncSetAttribute((const void*)gemm256_kernel<256, 0, 1, 512>,
                         cudaFuncAttributeMaxDynamicSharedMemorySize, SMEM_G);
    cudaFuncSetAttribute((const void*)gemm256_kernel<512, 2, 2, 256>,
                         cudaFuncAttributeMaxDynamicSharedMemorySize, SMEM_G);
    cudaFuncSetAttribute((const void*)gemm256_kernel<512, 1, 0, 256>,
                         cudaFuncAttributeMaxDynamicSharedMemorySize, SMEM_G);
    cudaFuncSetAttribute((const void*)gemm256_kernel<256, 2, 1, 512>,
                         cudaFuncAttributeMaxDynamicSharedMemorySize, SMEM_G);
    cudaFuncSetAttribute((const void*)gemm256_kernel<512, 2, 3, 256>,
                         cudaFuncAttributeMaxDynamicSharedMemorySize, SMEM_G);

    transpose5_kernel<<<dim3(16, 16, 5), dim3(32, 8)>>>(hf_w1, hf_w2, low_w, lf_w1, lf_w2,
                                                        hf_ln_w, lf_ln_w);
    fold_kernel<<<2, 256>>>(hf_w2, hf_ln_b, hf_b2, lf_w2, lf_ln_b, lf_b2);
    haar_z_kernel<<<dim3(4, 256, 16), 256>>>(xb);
    pool_small_kernel<<<dim3(512, 16), 256>>>(xsm);

    // hf chain
    gemm256_kernel<256, 0, 1, 512><<<dim3(M_HF / 64, 2), 256, SMEM_G>>>(
        (const float*)pz, wt + 0 * 512 * 256, hf_b1, nullptr, (float*)pH, sh, nullptr);
    gemm256_kernel<512, 2, 2, 256><<<dim3(M_HF / 64, 1), 256, SMEM_G>>>(
        (const float*)pH, wt + 1 * 512 * 256, bp + 0, hf_pr, (float*)palpha, sh, c1 + 0);

    // lf chain
    gemm256_kernel<512, 1, 0, 256><<<dim3(M_LF / 64, 1), 256, SMEM_G>>>(
        (const float*)pps, wt + 2 * 512 * 256, low_b, nullptr, (float*)pktok, nullptr, nullptr);
    gemm256_kernel<256, 2, 1, 512><<<dim3(M_LF / 64, 2), 256, SMEM_G>>>(
        (const float*)pktok, wt + 3 * 512 * 256, lf_b1, nullptr, (float*)pHlf, sl, nullptr);
    gemm256_kernel<512, 2, 3, 256><<<dim3(M_LF / 64, 1), 256, SMEM_G>>>(
        (const float*)pHlf, wt + 4 * 512 * 256, bp + 256, nullptr, (float*)pgate, sl, c1 + 256);

    final_kernel<<<dim3(16, 256, 16), 256>>>(xb, (float*)d_out);
}